// round 17
// baseline (speedup 1.0000x reference)
#include <cuda_runtime.h>

// MedianFilter: xs [B=4,T=32,N=128,D=32] f32, A [1,128,128] i32.
// Per (b,t,n,d): lower median over {prev-self (t>0), next-self (t<T-1),
//   xs[b,t,j,d] for j with (A+I)[n][j]!=0}.
//
// Exact, search-free selection (R16 algorithm, occupancy-restructured):
//  block = (frame, 2 channels), 128 threads, grid 2048 -> 12 blocks/SM.
//  Warps 0-1: blocked bitonic sort of one channel each (keys + row indices).
//  All 4 warps: P-build (P[n] = membership mask permuted to sorted order via
//  warp-shuffle 32x32 bit transposes of C = (A+I)^T columns).
//  Phase 2: thread = node; order-stats via register select-bit on P;
//  prev/next by the 5-candidate rank rule.

#define Bc 4
#define Tc 32
#define NTOT 128
#define Dc 32
#define NTH 128          // 4 warps per block
#define CPB 2            // channels per block
#define PSTR 9           // P row stride in words (odd -> conflict-free)

typedef unsigned u32;

__device__ u32 g_C[NTOT * 4];   // C[j].word[g]: bit n' = (A+I)[g*32+n'][j] != 0

__device__ __forceinline__ u32 f2u(float f) {
    u32 s = __float_as_uint(f);
    return s ^ ((u32)((int)s >> 31) | 0x80000000u);
}
__device__ __forceinline__ float u2f(u32 u) {
    u32 s = (u & 0x80000000u) ? (u ^ 0x80000000u) : ~u;
    return __uint_as_float(s);
}

// 32x32 bit-matrix transpose across a warp (lane = row, bits = cols)
__device__ __forceinline__ u32 transpose32(u32 x, int lane) {
    u32 y;
#define TSTEP(J, M)                                              \
    y = __shfl_xor_sync(0xFFFFFFFFu, x, J);                      \
    x = (lane & J) ? ((x & ~(M)) | ((y >> J) & (M)))             \
                   : ((x & (M)) | ((y & (M)) << J));
    TSTEP(16, 0x0000FFFFu)
    TSTEP(8,  0x00FF00FFu)
    TSTEP(4,  0x0F0F0F0Fu)
    TSTEP(2,  0x33333333u)
    TSTEP(1,  0x55555555u)
#undef TSTEP
    return x;
}

// position of q-th (0-based) set bit of v (q < popc(v))
__device__ __forceinline__ int sel_in_word(u32 v, int q) {
    int off = 0;
    int c;
    c = __popc(v & 0xFFFFu); if (q >= c) { q -= c; v >>= 16; off += 16; }
    c = __popc(v & 0xFFu);   if (q >= c) { q -= c; v >>= 8;  off += 8; }
    c = __popc(v & 0xFu);    if (q >= c) { q -= c; v >>= 4;  off += 4; }
    c = __popc(v & 0x3u);    if (q >= c) { q -= c; v >>= 2;  off += 2; }
    off += (int)(q >= (int)(v & 1u));
    return off;
}
// position of q-th set bit across 128-bit (w0..w3)
__device__ __forceinline__ int sel128(u32 w0, u32 w1, u32 w2, u32 w3, int q) {
    int base = 0;
    u32 cw = w0;
    int c = __popc(w0);
    if (q >= c) {
        q -= c; cw = w1; base = 32; c = __popc(w1);
        if (q >= c) {
            q -= c; cw = w2; base = 64; c = __popc(w2);
            if (q >= c) { q -= c; cw = w3; base = 96; }
        }
    }
    return base + sel_in_word(cw, q);
}

// ---------------- prep: C = (A + I)^T, wide (4 blocks x 1024) ---------------
__global__ void prep_kernel(const int* __restrict__ A)
{
    const int g    = blockIdx.x;          // node word group 0..3
    const int tid  = threadIdx.x;
    const int w    = tid >> 5;            // column quad 0..31
    const int lane = tid & 31;            // node offset within group

    int4 v = ((const int4*)A)[(g * 32 + lane) * 32 + w];   // A[g*32+lane][4w..4w+3]
    u32 b0 = __ballot_sync(0xFFFFFFFFu, v.x != 0);
    u32 b1 = __ballot_sync(0xFFFFFFFFu, v.y != 0);
    u32 b2 = __ballot_sync(0xFFFFFFFFu, v.z != 0);
    u32 b3 = __ballot_sync(0xFFFFFFFFu, v.w != 0);
    if (lane == 0) {
        u32 arr[4] = {b0, b1, b2, b3};
        #pragma unroll
        for (int jj = 0; jj < 4; jj++) {
            int j = w * 4 + jj;
            if ((j >> 5) == g) arr[jj] |= 1u << (j & 31);   // + I
            g_C[j * 4 + g] = arr[jj];
        }
    }
}

// in-thread compare-exchange (indices a < b); ascending if asc
#define CSW(a, b, asc)                                                     \
    {                                                                      \
        bool sw_ = (asc) ? (k[a] > k[b]) : (k[a] < k[b]);                  \
        if (sw_) {                                                         \
            u32 tk_ = k[a]; k[a] = k[b]; k[b] = tk_;                       \
            u32 tx_ = xi[a]; xi[a] = xi[b]; xi[b] = tx_;                   \
        }                                                                  \
    }

// ---------------- main ------------------------------------------------------
__global__ __launch_bounds__(NTH, 12)
void median_kernel(const float* __restrict__ xs, float* __restrict__ out)
{
    __shared__ u32 tile[CPB * 132];        // cur  [cl][row]
    __shared__ u32 pvt [NTOT * 3];         // prev [row][cl] stride 3 (INF if t==0)
    __shared__ u32 nxt [NTOT * 3];         // next [row][cl] stride 3
    __shared__ u32 skey[CPB * 132];        // sorted keys per channel
    __shared__ u32 xism[CPB * 32];         // sorted row indices (packed bytes)
    __shared__ u32 Csm [NTOT * 4];         // C columns
    __shared__ u32 Psm [NTOT * PSTR];      // P[n][cl][r] at n*9 + cl*4 + r

    const int bid  = blockIdx.x;
    const int bt   = bid >> 4;             // frame
    const int cg   = bid & 15;             // channel pair index (d = cg*2+cl)
    const int t    = bt & (Tc - 1);
    const int tid  = threadIdx.x;
    const int lane = tid & 31;
    const int w    = tid >> 5;

    const bool hasPrev = (t > 0);
    const bool hasNext = (t < Tc - 1);

    // ---- phase 0: stage tiles + C ----
    {
        const uint2* b2 = (const uint2*)xs;        // frame = 2048 uint2
        const int off = tid * 16 + cg;             // row tid, channel pair cg
        uint2 v = b2[(size_t)bt * 2048 + off];
        tile[0 * 132 + tid] = f2u(__uint_as_float(v.x));
        tile[1 * 132 + tid] = f2u(__uint_as_float(v.y));
        uint2 p = make_uint2(~0u, ~0u), q = p;
        if (hasPrev) {
            uint2 x = b2[(size_t)(bt - 1) * 2048 + off];
            p = make_uint2(f2u(__uint_as_float(x.x)), f2u(__uint_as_float(x.y)));
        }
        if (hasNext) {
            uint2 x = b2[(size_t)(bt + 1) * 2048 + off];
            q = make_uint2(f2u(__uint_as_float(x.x)), f2u(__uint_as_float(x.y)));
        }
        pvt[tid * 3 + 0] = p.x; pvt[tid * 3 + 1] = p.y;
        nxt[tid * 3 + 0] = q.x; nxt[tid * 3 + 1] = q.y;
        ((uint4*)Csm)[tid] = ((const uint4*)g_C)[tid];
    }
    __syncthreads();

    // ---- phase 1a: warps 0-1 sort channel w (blocked layout) ----
    if (w < CPB) {
        u32 k[4], xi[4];
        {
            uint4 kv = ((const uint4*)(tile + w * 132))[lane];
            k[0] = kv.x; k[1] = kv.y; k[2] = kv.z; k[3] = kv.w;
            xi[0] = (u32)(lane * 4 + 0); xi[1] = (u32)(lane * 4 + 1);
            xi[2] = (u32)(lane * 4 + 2); xi[3] = (u32)(lane * 4 + 3);
        }

        // size 2: pair (0,1) asc, (2,3) desc
        CSW(0, 1, true)
        CSW(2, 3, false)
        // size 4: dir = ((lane & 1) == 0)
        {
            bool a4 = (lane & 1) == 0;
            CSW(0, 2, a4) CSW(1, 3, a4) CSW(0, 1, a4) CSW(2, 3, a4)
        }
        // sizes 8..128
        #pragma unroll
        for (int sz = 8; sz <= 128; sz <<= 1) {
            bool asc = (lane & (sz >> 2)) == 0;
            #pragma unroll
            for (int d = sz >> 1; d >= 4; d >>= 1) {
                int dd = d >> 2;
                bool keepmin = (((lane & dd) == 0) == asc);
                #pragma unroll
                for (int r = 0; r < 4; r++) {
                    u32 pk = __shfl_xor_sync(0xFFFFFFFFu, k[r],  dd);
                    u32 px = __shfl_xor_sync(0xFFFFFFFFu, xi[r], dd);
                    bool less = pk < k[r], grt = pk > k[r];
                    bool take = keepmin ? less : grt;
                    if (take) { k[r] = pk; xi[r] = px; }
                }
            }
            CSW(0, 2, asc) CSW(1, 3, asc) CSW(0, 1, asc) CSW(2, 3, asc)
        }

        ((uint4*)(skey + w * 132))[lane] = make_uint4(k[0], k[1], k[2], k[3]);
        xism[w * 32 + lane] = xi[0] | (xi[1] << 8) | (xi[2] << 16) | (xi[3] << 24);
    }
    __syncthreads();

    // ---- phase 1b: all 4 warps build P (warp -> (cl = w>>1, 2 rp each)) ----
    {
        const int cl = w >> 1;
        #pragma unroll
        for (int rr = 0; rr < 2; rr++) {
            const int rp = (w & 1) * 2 + rr;
            u32 xw = xism[cl * 32 + rp * 8 + (lane >> 2)];
            u32 xv = (xw >> ((lane & 3) * 8)) & 255u;   // row at pos rp*32+lane
            uint4 col = ((const uint4*)Csm)[xv];
            #pragma unroll
            for (int g = 0; g < 4; g++) {
                u32 x = (g == 0) ? col.x : (g == 1) ? col.y
                      : (g == 2) ? col.z : col.w;
                x = transpose32(x, lane);       // lane -> node offset, bits -> pos
                Psm[(g * 32 + lane) * PSTR + cl * 4 + rp] = x;
            }
        }
    }
    __syncthreads();

    // ---- phase 2: thread = node; 5-candidate exact selection x 2 channels --
    const int n = tid;
    u32 P[CPB][4];
    #pragma unroll
    for (int cl = 0; cl < CPB; cl++)
        #pragma unroll
        for (int r = 0; r < 4; r++)
            P[cl][r] = Psm[n * PSTR + cl * 4 + r];

    const int kpop = __popc(P[0][0]) + __popc(P[0][1])
                   + __popc(P[0][2]) + __popc(P[0][3]);
    const int e = (int)hasPrev + (int)hasNext;
    const int m = (kpop + e - 1) >> 1;

    float res[CPB];
    #pragma unroll
    for (int cl = 0; cl < CPB; cl++) {
        const u32 p  = pvt[n * 3 + cl];
        const u32 nx = nxt[n * 3 + cl];
        const u32* S = skey + cl * 132;

        // member order stats around the median (sentinels outside range)
        u32 x0 = 0u, x1 = 0u, x2 = 0xFFFFFFFFu;
        if (m >= 2)    x0 = S[sel128(P[cl][0], P[cl][1], P[cl][2], P[cl][3], m - 2)];
        if (m >= 1)    x1 = S[sel128(P[cl][0], P[cl][1], P[cl][2], P[cl][3], m - 1)];
        if (m < kpop)  x2 = S[sel128(P[cl][0], P[cl][1], P[cl][2], P[cl][3], m)];

        const int c2 = (int)(p < x2) + (int)(nx < x2);
        const int c1 = (int)(p < x1) + (int)(nx < x1);
        const int c0 = (int)(p < x0) + (int)(nx < x0);

        u32 ans;
        if (c2 == 0)      ans = x2;                 // rank(M[m])   = m
        else if (c1 == 1) ans = x1;                 // rank(M[m-1]) = m
        else if (c0 == 2) ans = x0;                 // rank(M[m-2]) = m
        else if (c1 == 0) ans = (nx < p) ? nx : p;  // temporal in (M[m-1],M[m])
        else              ans = (p <= nx) ? nx : p; // temporal in (M[m-2],M[m-1])
        res[cl] = u2f(ans);
    }

    ((float2*)out)[(size_t)bt * 2048 + n * 16 + cg] = make_float2(res[0], res[1]);
}

extern "C" void kernel_launch(void* const* d_in, const int* in_sizes, int n_in,
                              void* d_out, int out_size)
{
    const float* xs  = (const float*)d_in[0];
    const int*   A   = (const int*)d_in[1];
    float*       out = (float*)d_out;
    (void)in_sizes; (void)n_in; (void)out_size;

    cudaFuncSetAttribute(median_kernel,
                         cudaFuncAttributePreferredSharedMemoryCarveout, 100);
    prep_kernel<<<4, 1024>>>(A);
    median_kernel<<<Bc * Tc * 16, NTH>>>(xs, out);
}